// round 1
// baseline (speedup 1.0000x reference)
#include <cuda_runtime.h>
#include <math.h>
#include <float.h>

// ---------------- problem constants ----------------
#define SQ   2048      // sequence length S
#define DM   2048
#define H    16
#define DN   128
#define DRR  64
#define DV   128
#define QRr  1536
#define KRr  512
#define HIi  32
#define DIi  128
#define TOPK 512
#define DQK  192       // DN + DR

#define INV_SQRT_DQK 0.07216878364870322f   // 192^-0.5
#define INV_SQRT_DI  0.08838834764831845f   // 128^-0.5
#define INV_SQRT_HI  0.17677669529663687f   // 32^-0.5

// ---------------- scratch (device globals; no allocations allowed) ----------------
__device__ float g_qr   [SQ * QRr];
__device__ float g_q    [SQ * H * DQK];
__device__ float g_kvall[SQ * (KRr + DRR)];
__device__ float g_kv   [SQ * KRr];
__device__ float g_kpe  [SQ * DRR];
__device__ float g_kvp  [SQ * H * (DN + DV)];
__device__ float g_k    [SQ * H * DQK];
__device__ float g_v    [SQ * H * DV];
__device__ float g_qi   [SQ * HIi * DIi];
__device__ float g_ki   [SQ * DIi];
__device__ float g_wts  [SQ * HIi];
__device__ float g_iscore[(size_t)SQ * SQ];
__device__ int   g_tidx [SQ * TOPK];
__device__ int   g_tcnt [SQ];
__device__ float g_attn [SQ * H * DV];

// ---------------- SGEMM (C[M,N] = A[M,K] * B[N,K]^T), 128x128x16, 8x8/thread ----------------
__global__ __launch_bounds__(256) void sgemm_nt(
    const float* __restrict__ A, const float* __restrict__ B, float* __restrict__ C,
    int M, int N, int K)
{
    __shared__ float As[16][128];
    __shared__ float Bs[16][128];
    const int bm = blockIdx.x * 128, bn = blockIdx.y * 128;
    const int tid = threadIdx.x;
    const int lr = tid >> 2;             // 0..63
    const int lc = (tid & 3) << 2;       // 0,4,8,12
    const int tm = (tid >> 4) << 3;      // 0..120
    const int tn = (tid & 15) << 3;      // 0..120
    float acc[8][8];
#pragma unroll
    for (int i = 0; i < 8; i++)
#pragma unroll
        for (int j = 0; j < 8; j++) acc[i][j] = 0.f;

    for (int k0 = 0; k0 < K; k0 += 16) {
#pragma unroll
        for (int i = 0; i < 2; i++) {
            int r = lr + i * 64;
            float4 va = make_float4(0.f, 0.f, 0.f, 0.f);
            float4 vb = make_float4(0.f, 0.f, 0.f, 0.f);
            if (bm + r < M) va = *(const float4*)(A + (size_t)(bm + r) * K + k0 + lc);
            if (bn + r < N) vb = *(const float4*)(B + (size_t)(bn + r) * K + k0 + lc);
            As[lc + 0][r] = va.x; As[lc + 1][r] = va.y; As[lc + 2][r] = va.z; As[lc + 3][r] = va.w;
            Bs[lc + 0][r] = vb.x; Bs[lc + 1][r] = vb.y; Bs[lc + 2][r] = vb.z; Bs[lc + 3][r] = vb.w;
        }
        __syncthreads();
#pragma unroll
        for (int kk = 0; kk < 16; kk++) {
            float a[8], b[8];
#pragma unroll
            for (int i = 0; i < 8; i++) a[i] = As[kk][tm + i];
#pragma unroll
            for (int j = 0; j < 8; j++) b[j] = Bs[kk][tn + j];
#pragma unroll
            for (int i = 0; i < 8; i++)
#pragma unroll
                for (int j = 0; j < 8; j++)
                    acc[i][j] += a[i] * b[j];
        }
        __syncthreads();
    }
#pragma unroll
    for (int i = 0; i < 8; i++) {
        int m = bm + tm + i;
        if (m >= M) continue;
#pragma unroll
        for (int j = 0; j < 8; j++) {
            int n = bn + tn + j;
            if (n < N) C[(size_t)m * N + n] = acc[i][j];
        }
    }
}

// ---------------- warp-per-output GEMM for small N (N=128, N=32) ----------------
__global__ void gemm_warpdot(const float* __restrict__ A, const float* __restrict__ B,
                             float* __restrict__ C, int M, int N, int K, float scale)
{
    int gw = (int)((blockIdx.x * (size_t)blockDim.x + threadIdx.x) >> 5);
    int lane = threadIdx.x & 31;
    if (gw >= M * N) return;
    int m = gw / N, n = gw % N;
    const float* a = A + (size_t)m * K;
    const float* b = B + (size_t)n * K;
    float s = 0.f;
    for (int k = lane * 4; k < K; k += 128) {
        float4 va = *(const float4*)(a + k);
        float4 vb = *(const float4*)(b + k);
        s += va.x * vb.x + va.y * vb.y + va.z * vb.z + va.w * vb.w;
    }
#pragma unroll
    for (int o = 16; o; o >>= 1) s += __shfl_xor_sync(0xffffffffu, s, o);
    if (lane == 0) C[(size_t)m * N + n] = s * scale;
}

// ---------------- row rmsnorm ----------------
__global__ void rmsnorm_kernel(const float* __restrict__ in, const float* __restrict__ w,
                               float* __restrict__ out, int cols, int in_stride, int out_stride,
                               float eps)
{
    int row = blockIdx.x;
    const float* x = in + (size_t)row * in_stride;
    float* y = out + (size_t)row * out_stride;
    float ss = 0.f;
    for (int i = threadIdx.x; i < cols; i += blockDim.x) { float v = x[i]; ss += v * v; }
    __shared__ float red[32];
    int lane = threadIdx.x & 31, wp = threadIdx.x >> 5;
#pragma unroll
    for (int o = 16; o; o >>= 1) ss += __shfl_xor_sync(0xffffffffu, ss, o);
    if (lane == 0) red[wp] = ss;
    __syncthreads();
    int nw = blockDim.x >> 5;
    float tot = 0.f;
    for (int i = 0; i < nw; i++) tot += red[i];
    float inv = rsqrtf(tot / (float)cols + eps);
    for (int i = threadIdx.x; i < cols; i += blockDim.x) y[i] = x[i] * inv * w[i];
}

// ---------------- layernorm for ki (cols = 128), 128 threads ----------------
__global__ void layernorm128_kernel(float* __restrict__ x, const float* __restrict__ w,
                                    const float* __restrict__ b)
{
    int row = blockIdx.x;
    float* p = x + (size_t)row * DIi;
    int tid = threadIdx.x, lane = tid & 31, wp = tid >> 5;
    float v = p[tid];
    __shared__ float red[4];
    float t = v;
#pragma unroll
    for (int o = 16; o; o >>= 1) t += __shfl_xor_sync(0xffffffffu, t, o);
    if (lane == 0) red[wp] = t;
    __syncthreads();
    float mean = (red[0] + red[1] + red[2] + red[3]) * (1.f / 128.f);
    __syncthreads();
    float d = v - mean;
    t = d * d;
#pragma unroll
    for (int o = 16; o; o >>= 1) t += __shfl_xor_sync(0xffffffffu, t, o);
    if (lane == 0) red[wp] = t;
    __syncthreads();
    float var = (red[0] + red[1] + red[2] + red[3]) * (1.f / 128.f);
    p[tid] = d * rsqrtf(var + 1e-5f) * w[tid] + b[tid];
}

// ---------------- rope kernels ----------------
__global__ void rope_inter_q(float* __restrict__ q, const float* __restrict__ c,
                             const float* __restrict__ sn)
{
    int n = blockIdx.x * blockDim.x + threadIdx.x;
    if (n >= SQ * H * 32) return;
    int s = n / (H * 32); int r = n % (H * 32); int h = r / 32; int i = r % 32;
    float* p = q + (size_t)s * (H * DQK) + h * DQK + DN + 2 * i;
    float x0 = p[0], x1 = p[1];
    float cc = c[s * 32 + i], ss = sn[s * 32 + i];
    p[0] = x0 * cc - x1 * ss;
    p[1] = x0 * ss + x1 * cc;
}

__global__ void rope_inter_kpe(const float* __restrict__ kvall, const float* __restrict__ c,
                               const float* __restrict__ sn, float* __restrict__ kpe)
{
    int n = blockIdx.x * blockDim.x + threadIdx.x;
    if (n >= SQ * 32) return;
    int s = n / 32, i = n % 32;
    const float* p = kvall + (size_t)s * (KRr + DRR) + KRr + 2 * i;
    float x0 = p[0], x1 = p[1];
    float cc = c[s * 32 + i], ss = sn[s * 32 + i];
    kpe[(size_t)s * DRR + 2 * i]     = x0 * cc - x1 * ss;
    kpe[(size_t)s * DRR + 2 * i + 1] = x0 * ss + x1 * cc;
}

__global__ void rope_half_qi_kernel(float* __restrict__ qi, const float* __restrict__ c,
                                    const float* __restrict__ sn)
{
    int n = blockIdx.x * blockDim.x + threadIdx.x;
    if (n >= SQ * HIi * 32) return;
    int s = n / (HIi * 32); int r = n % (HIi * 32); int h = r / 32; int i = r % 32;
    float* p = qi + (size_t)s * (HIi * DIi) + h * DIi;
    float x0 = p[i], x1 = p[i + 32];
    float cc = c[s * 32 + i], ss = sn[s * 32 + i];
    p[i]      = x0 * cc - x1 * ss;
    p[i + 32] = x0 * ss + x1 * cc;
}

__global__ void rope_half_ki_kernel(float* __restrict__ ki, const float* __restrict__ c,
                                    const float* __restrict__ sn)
{
    int n = blockIdx.x * blockDim.x + threadIdx.x;
    if (n >= SQ * 32) return;
    int s = n / 32, i = n % 32;
    float* p = ki + (size_t)s * DIi;
    float x0 = p[i], x1 = p[i + 32];
    float cc = c[s * 32 + i], ss = sn[s * 32 + i];
    p[i]      = x0 * cc - x1 * ss;
    p[i + 32] = x0 * ss + x1 * cc;
}

// ---------------- pack k / v from kvp + kpe ----------------
__global__ void pack_k_kernel(const float* __restrict__ kvp, const float* __restrict__ kpe,
                              float* __restrict__ k)
{
    int n = blockIdx.x * blockDim.x + threadIdx.x;
    if (n >= SQ * H * DQK) return;
    int s = n / (H * DQK); int r = n % (H * DQK); int h = r / DQK; int d = r % DQK;
    k[n] = (d < DN) ? kvp[(size_t)s * (H * (DN + DV)) + h * (DN + DV) + d]
                    : kpe[(size_t)s * DRR + (d - DN)];
}

__global__ void pack_v_kernel(const float* __restrict__ kvp, float* __restrict__ v)
{
    int n = blockIdx.x * blockDim.x + threadIdx.x;
    if (n >= SQ * H * DV) return;
    int s = n / (H * DV); int r = n % (H * DV); int h = r / DV; int d = r % DV;
    v[n] = kvp[(size_t)s * (H * (DN + DV)) + h * (DN + DV) + DN + d];
}

// ---------------- indexer scores: iscore[s][t] = sum_h relu(qi.ki/sqrt(DI)) * wts ----------------
__global__ __launch_bounds__(256) void indexer_kernel(
    const float* __restrict__ qi, const float* __restrict__ ki,
    const float* __restrict__ wts, float* __restrict__ iscore)
{
    int t0 = blockIdx.x * 32, s0 = blockIdx.y * 32;
    if (t0 > s0 + 31) return;   // fully above the causal diagonal: never read
    __shared__ float qs[32][33];
    __shared__ float ks[32][33];
    __shared__ float ws[32][32];
    int tid = threadIdx.x;
    for (int i = tid; i < 32 * 32; i += 256)
        ws[i >> 5][i & 31] = wts[(size_t)(s0 + (i >> 5)) * HIi + (i & 31)];
    int tl = tid & 31;
    int sg = tid >> 5;           // 0..7
    int lr = tid >> 3;           // 0..31
    int lc = (tid & 7) << 2;     // 0..28
    float score[4] = {0.f, 0.f, 0.f, 0.f};
    for (int h = 0; h < HIi; h++) {
        float dotv[4] = {0.f, 0.f, 0.f, 0.f};
        for (int d0 = 0; d0 < DIi; d0 += 32) {
            __syncthreads();
            float4 kv4 = *(const float4*)(ki + (size_t)(t0 + lr) * DIi + d0 + lc);
            ks[lr][lc] = kv4.x; ks[lr][lc + 1] = kv4.y; ks[lr][lc + 2] = kv4.z; ks[lr][lc + 3] = kv4.w;
            float4 qv4 = *(const float4*)(qi + (size_t)(s0 + lr) * (HIi * DIi) + h * DIi + d0 + lc);
            qs[lr][lc] = qv4.x; qs[lr][lc + 1] = qv4.y; qs[lr][lc + 2] = qv4.z; qs[lr][lc + 3] = qv4.w;
            __syncthreads();
#pragma unroll
            for (int dd = 0; dd < 32; dd++) {
                float kk = ks[tl][dd];
                dotv[0] += qs[sg][dd] * kk;
                dotv[1] += qs[sg + 8][dd] * kk;
                dotv[2] += qs[sg + 16][dd] * kk;
                dotv[3] += qs[sg + 24][dd] * kk;
            }
        }
#pragma unroll
        for (int i = 0; i < 4; i++)
            score[i] += fmaxf(dotv[i] * INV_SQRT_DI, 0.f) * ws[sg + (i << 3)][h];
    }
    int t = t0 + tl;
#pragma unroll
    for (int i = 0; i < 4; i++) {
        int s = s0 + sg + (i << 3);
        if (t <= s) iscore[(size_t)s * SQ + t] = score[i];
    }
}

// ---------------- exact top-512 per row: radix select + deterministic ordered fill ----------------
__device__ __forceinline__ unsigned forder(float f)
{
    unsigned u = __float_as_uint(f);
    return (u & 0x80000000u) ? ~u : (u | 0x80000000u);
}

__global__ __launch_bounds__(256) void topk_kernel(const float* __restrict__ iscore,
                                                   int* __restrict__ tidx, int* __restrict__ tcnt)
{
    int s = blockIdx.x;
    int n = s + 1;
    int tid = threadIdx.x;
    const float* row = iscore + (size_t)s * SQ;
    int* out = tidx + (size_t)s * TOPK;
    if (n <= TOPK) {                 // all causal keys selected
        for (int t = tid; t < n; t += 256) out[t] = t;
        if (tid == 0) tcnt[s] = n;
        return;
    }
    __shared__ int hist[256];
    __shared__ unsigned s_pref;
    __shared__ int s_k;
    if (tid == 0) { s_pref = 0u; s_k = TOPK; }
    __syncthreads();
    for (int pass = 0; pass < 4; pass++) {
        int sh = 24 - 8 * pass;
        unsigned hmask = (pass == 0) ? 0u : (0xFFFFFFFFu << (sh + 8));
        hist[tid] = 0;
        __syncthreads();
        unsigned pref = s_pref;
        for (int t = tid; t < n; t += 256) {
            unsigned u = forder(row[t]);
            if ((u & hmask) == pref) atomicAdd(&hist[(u >> sh) & 255u], 1);
        }
        __syncthreads();
        if (tid == 0) {
            int k = s_k, c = 0, j = 255;
            for (; j >= 0; j--) {
                if (c + hist[j] >= k) break;
                c += hist[j];
            }
            s_k = k - c;
            s_pref = s_pref | ((unsigned)j << sh);
        }
        __syncthreads();
    }
    unsigned uthr = s_pref;
    // deterministic ascending-t fill of strictly-greater elements via prefix scan
    int chunk = (n + 255) / 256;
    int beg = tid * chunk;
    int end = beg + chunk; if (end > n) end = n;
    int cntg = 0;
    for (int t = beg; t < end; t++) if (forder(row[t]) > uthr) cntg++;
    __shared__ int sc[256];
    sc[tid] = cntg;
    __syncthreads();
    for (int o = 1; o < 256; o <<= 1) {
        int v = (tid >= o) ? sc[tid - o] : 0;
        __syncthreads();
        sc[tid] += v;
        __syncthreads();
    }
    int off = sc[tid] - cntg;
    int total = sc[255];
    for (int t = beg; t < end; t++)
        if (forder(row[t]) > uthr) out[off++] = t;
    __syncthreads();
    if (tid == 0) {
        // ties at threshold: lowest t first (matches jax top_k tie-breaking)
        int c = total, q = s_k;
        for (int t = 0; t < n && q > 0; t++) {
            if (forder(row[t]) == uthr) { out[c++] = t; q--; }
        }
        tcnt[s] = TOPK;
    }
}

// ---------------- sparse attention per (s, h) ----------------
__global__ __launch_bounds__(256) void attn_kernel(
    const float* __restrict__ q, const float* __restrict__ k, const float* __restrict__ v,
    const int* __restrict__ tidx, const int* __restrict__ tcnt, float* __restrict__ out)
{
    int s = blockIdx.x, h = blockIdx.y;
    int tid = threadIdx.x, lane = tid & 31, wp = tid >> 5;
    int n = tcnt[s];
    __shared__ float qs[DQK];
    __shared__ float lg[TOPK];
    __shared__ int   ix[TOPK];
    __shared__ float red[8];
    __shared__ float accs[128];
    if (tid < DQK) qs[tid] = q[(size_t)s * (H * DQK) + h * DQK + tid];
    for (int j = tid; j < n; j += 256) ix[j] = tidx[(size_t)s * TOPK + j];
    __syncthreads();
    // logits: one warp per key
    for (int j = wp; j < n; j += 8) {
        const float* kp = k + (size_t)ix[j] * (H * DQK) + h * DQK;
        float d = 0.f;
#pragma unroll
        for (int c = 0; c < DQK / 32; c++) d += qs[lane + c * 32] * kp[lane + c * 32];
#pragma unroll
        for (int o = 16; o; o >>= 1) d += __shfl_xor_sync(0xffffffffu, d, o);
        if (lane == 0) lg[j] = d * INV_SQRT_DQK;
    }
    __syncthreads();
    // softmax
    float m = -FLT_MAX;
    for (int j = tid; j < n; j += 256) m = fmaxf(m, lg[j]);
#pragma unroll
    for (int o = 16; o; o >>= 1) m = fmaxf(m, __shfl_xor_sync(0xffffffffu, m, o));
    if (lane == 0) red[wp] = m;
    __syncthreads();
    m = red[0];
#pragma unroll
    for (int i = 1; i < 8; i++) m = fmaxf(m, red[i]);
    __syncthreads();
    float ssum = 0.f;
    for (int j = tid; j < n; j += 256) { float e = __expf(lg[j] - m); lg[j] = e; ssum += e; }
#pragma unroll
    for (int o = 16; o; o >>= 1) ssum += __shfl_xor_sync(0xffffffffu, ssum, o);
    if (lane == 0) red[wp] = ssum;
    __syncthreads();
    float tot = 0.f;
#pragma unroll
    for (int i = 0; i < 8; i++) tot += red[i];
    float inv = 1.f / tot;
    // weighted V sum: 2 halves of threads split the key list
    int d = tid & 127, half = tid >> 7;
    float acc = 0.f;
#pragma unroll 4
    for (int j = half; j < n; j += 2)
        acc += lg[j] * v[(size_t)ix[j] * (H * DV) + h * DV + d];
    if (half == 1) accs[d] = acc;
    __syncthreads();
    if (half == 0)
        out[(size_t)s * (H * DV) + h * DV + d] = (acc + accs[d]) * inv;
}

// ---------------- host launcher ----------------
extern "C" void kernel_launch(void* const* d_in, const int* in_sizes, int n_in,
                              void* d_out, int out_size)
{
    const float *hidden, *cosp, *sinp, *wq_a, *q_norm_w, *wq_b, *wkv_a, *kv_norm_w,
                *wkv_b, *wo, *idx_wq_b, *idx_wk, *idx_kn_w, *idx_kn_b, *idx_wproj;
    if (n_in >= 2 && in_sizes[1] == 3145728) {
        // setup_inputs() dict order
        hidden    = (const float*)d_in[0];
        wq_a      = (const float*)d_in[1];
        q_norm_w  = (const float*)d_in[2];
        wq_b      = (const float*)d_in[3];
        wkv_a     = (const float*)d_in[4];
        kv_norm_w = (const float*)d_in[5];
        wkv_b     = (const float*)d_in[6];
        wo        = (const float*)d_in[7];
        idx_wq_b  = (const float*)d_in[8];
        idx_wk    = (const float*)d_in[9];
        idx_kn_w  = (const float*)d_in[10];
        idx_kn_b  = (const float*)d_in[11];
        idx_wproj = (const float*)d_in[12];
        cosp      = (const float*)d_in[13];
        sinp      = (const float*)d_in[14];
        // d_in[15] = mask (causal; hardcoded)
    } else {
        // reference() signature order
        hidden    = (const float*)d_in[0];
        cosp      = (const float*)d_in[1];
        sinp      = (const float*)d_in[2];
        // d_in[3] = mask
        wq_a      = (const float*)d_in[4];
        q_norm_w  = (const float*)d_in[5];
        wq_b      = (const float*)d_in[6];
        wkv_a     = (const float*)d_in[7];
        kv_norm_w = (const float*)d_in[8];
        wkv_b     = (const float*)d_in[9];
        wo        = (const float*)d_in[10];
        idx_wq_b  = (const float*)d_in[11];
        idx_wk    = (const float*)d_in[12];
        idx_kn_w  = (const float*)d_in[13];
        idx_kn_b  = (const float*)d_in[14];
        idx_wproj = (const float*)d_in[15];
    }

    float *qr, *q, *kvall, *kv, *kpe, *kvp, *k, *v, *qi, *ki, *wtsb, *iscore, *attnb;
    int *tix, *tcn;
    cudaGetSymbolAddress((void**)&qr,    g_qr);
    cudaGetSymbolAddress((void**)&q,     g_q);
    cudaGetSymbolAddress((void**)&kvall, g_kvall);
    cudaGetSymbolAddress((void**)&kv,    g_kv);
    cudaGetSymbolAddress((void**)&kpe,   g_kpe);
    cudaGetSymbolAddress((void**)&kvp,   g_kvp);
    cudaGetSymbolAddress((void**)&k,     g_k);
    cudaGetSymbolAddress((void**)&v,     g_v);
    cudaGetSymbolAddress((void**)&qi,    g_qi);
    cudaGetSymbolAddress((void**)&ki,    g_ki);
    cudaGetSymbolAddress((void**)&wtsb,  g_wts);
    cudaGetSymbolAddress((void**)&iscore,g_iscore);
    cudaGetSymbolAddress((void**)&attnb, g_attn);
    cudaGetSymbolAddress((void**)&tix,   g_tidx);
    cudaGetSymbolAddress((void**)&tcn,   g_tcnt);

    // 1. qr = rmsnorm(hidden @ wq_a.T)
    sgemm_nt<<<dim3(16, 12), 256>>>(hidden, wq_a, qr, SQ, QRr, DM);
    rmsnorm_kernel<<<SQ, 256>>>(qr, q_norm_w, qr, QRr, QRr, QRr, 1e-6f);

    // 2. q = rope(qr @ wq_b.T)
    sgemm_nt<<<dim3(16, 24), 256>>>(qr, wq_b, q, SQ, H * DQK, QRr);
    rope_inter_q<<<(SQ * H * 32 + 255) / 256, 256>>>(q, cosp, sinp);

    // 3. kv_all = hidden @ wkv_a.T ; kv = rmsnorm(kv_all[:KR]); kpe = rope(kv_all[KR:])
    sgemm_nt<<<dim3(16, 5), 256>>>(hidden, wkv_a, kvall, SQ, KRr + DRR, DM);
    rmsnorm_kernel<<<SQ, 256>>>(kvall, kv_norm_w, kv, KRr, KRr + DRR, KRr, 1e-6f);
    rope_inter_kpe<<<(SQ * 32 + 255) / 256, 256>>>(kvall, cosp, sinp, kpe);

    // 4. kvp = kv @ wkv_b.T ; split into k (with kpe) and v
    sgemm_nt<<<dim3(16, 32), 256>>>(kv, wkv_b, kvp, SQ, H * (DN + DV), KRr);
    pack_k_kernel<<<(SQ * H * DQK + 255) / 256, 256>>>(kvp, kpe, k);
    pack_v_kernel<<<(SQ * H * DV + 255) / 256, 256>>>(kvp, v);

    // 5. qi = rope_half(qr @ idx_wq_b.T)
    sgemm_nt<<<dim3(16, 32), 256>>>(qr, idx_wq_b, qi, SQ, HIi * DIi, QRr);
    rope_half_qi_kernel<<<(SQ * HIi * 32 + 255) / 256, 256>>>(qi, cosp, sinp);

    // 6. ki = rope_half(layernorm(hidden @ idx_wk.T))
    gemm_warpdot<<<(SQ * DIi * 32) / 256, 256>>>(hidden, idx_wk, ki, SQ, DIi, DM, 1.f);
    layernorm128_kernel<<<SQ, 128>>>(ki, idx_kn_w, idx_kn_b);
    rope_half_ki_kernel<<<(SQ * 32 + 255) / 256, 256>>>(ki, cosp, sinp);

    // 7. wts = hidden @ idx_wproj.T * HI^-0.5
    gemm_warpdot<<<(SQ * HIi * 32) / 256, 256>>>(hidden, idx_wproj, wtsb, SQ, HIi, DM, INV_SQRT_HI);

    // 8. indexer scores (causal)
    indexer_kernel<<<dim3(64, 64), 256>>>(qi, ki, wtsb, iscore);

    // 9. exact top-512 per row
    topk_kernel<<<SQ, 256>>>(iscore, tix, tcn);

    // 10. sparse attention
    attn_kernel<<<dim3(SQ, H), 256>>>(q, k, v, tix, tcn, attnb);

    // 11. output projection
    sgemm_nt<<<dim3(16, 16), 256>>>(attnb, wo, (float*)d_out, SQ, DM, DM);
}

// round 5
// speedup vs baseline: 1.2934x; 1.2934x over previous
#include <cuda_runtime.h>
#include <cuda_bf16.h>
#include <math.h>
#include <float.h>
#include <stdint.h>

// ---------------- problem constants ----------------
#define SQ   2048
#define DM   2048
#define H    16
#define DN   128
#define DRR  64
#define DV   128
#define QRr  1536
#define KRr  512
#define HIi  32
#define DIi  128
#define TOPK 512
#define DQK  192

#define INV_SQRT_DQK 0.07216878364870322f
#define INV_SQRT_DI  0.08838834764831845f
#define INV_SQRT_HI  0.17677669529663687f

// ---------------- scratch ----------------
__device__ float g_qr   [SQ * QRr];
__device__ float g_q    [SQ * H * DQK];
__device__ float g_kvall[SQ * (KRr + DRR)];
__device__ float g_kv   [SQ * KRr];
__device__ float g_kpe  [SQ * DRR];
__device__ float g_kvp  [SQ * H * (DN + DV)];
__device__ float g_k    [SQ * H * DQK];
__device__ float g_v    [SQ * H * DV];
__device__ float g_qi   [SQ * HIi * DIi];
__device__ float g_ki   [SQ * DIi];
__device__ float g_wts  [SQ * HIi];
__device__ float g_iscore[(size_t)SQ * SQ];
__device__ int   g_tidx [SQ * TOPK];
__device__ int   g_tcnt [SQ];
__device__ float g_attn [SQ * H * DV];

// ---------------- packed fp32x2 FMA helpers (exact fp32 RN per lane) ----------------
__device__ __forceinline__ unsigned long long pk2(float x, float y)
{
    unsigned long long r;
    asm("mov.b64 %0, {%1, %2};" : "=l"(r) : "f"(x), "f"(y));
    return r;
}
__device__ __forceinline__ void fma2(unsigned long long &c, unsigned long long a, unsigned long long b)
{
    asm("fma.rn.f32x2 %0, %1, %2, %0;" : "+l"(c) : "l"(a), "l"(b));
}
__device__ __forceinline__ float2 upk2(unsigned long long v)
{
    float2 f;
    asm("mov.b64 {%0, %1}, %2;" : "=f"(f.x), "=f"(f.y) : "l"(v));
    return f;
}

// ---------------- SGEMM (C[M,N]=A[M,K]*B[N,K]^T), 128x128x16, fp32x2 FFMA2 ----------------
// Per-element accumulation order identical to the scalar fp32 baseline:
// each acc[i][j] is its own RN-FMA chain over k=0..K-1 in order -> bit-identical.
__global__ __launch_bounds__(256) void sgemm_nt(
    const float* __restrict__ A, const float* __restrict__ B, float* __restrict__ C,
    int M, int N, int K)
{
    __shared__ float As[16][128];
    __shared__ float Bs[16][128];
    const int bm = blockIdx.x * 128, bn = blockIdx.y * 128;
    const int tid = threadIdx.x;
    const int lr = tid >> 2;
    const int lc = (tid & 3) << 2;
    const int tm = (tid >> 4) << 3;
    const int tn = (tid & 15) << 3;
    unsigned long long acc2[8][4];
#pragma unroll
    for (int i = 0; i < 8; i++)
#pragma unroll
        for (int j = 0; j < 4; j++) acc2[i][j] = 0ULL;

    for (int k0 = 0; k0 < K; k0 += 16) {
#pragma unroll
        for (int i = 0; i < 2; i++) {
            int r = lr + i * 64;
            float4 va = make_float4(0.f, 0.f, 0.f, 0.f);
            float4 vb = make_float4(0.f, 0.f, 0.f, 0.f);
            if (bm + r < M) va = *(const float4*)(A + (size_t)(bm + r) * K + k0 + lc);
            if (bn + r < N) vb = *(const float4*)(B + (size_t)(bn + r) * K + k0 + lc);
            As[lc + 0][r] = va.x; As[lc + 1][r] = va.y; As[lc + 2][r] = va.z; As[lc + 3][r] = va.w;
            Bs[lc + 0][r] = vb.x; Bs[lc + 1][r] = vb.y; Bs[lc + 2][r] = vb.z; Bs[lc + 3][r] = vb.w;
        }
        __syncthreads();
#pragma unroll
        for (int kk = 0; kk < 16; kk++) {
            float a[8], b[8];
#pragma unroll
            for (int i = 0; i < 8; i++) a[i] = As[kk][tm + i];
#pragma unroll
            for (int j = 0; j < 8; j++) b[j] = Bs[kk][tn + j];
            unsigned long long b2[4];
#pragma unroll
            for (int j = 0; j < 4; j++) b2[j] = pk2(b[2 * j], b[2 * j + 1]);
#pragma unroll
            for (int i = 0; i < 8; i++) {
                unsigned long long a2 = pk2(a[i], a[i]);
#pragma unroll
                for (int j = 0; j < 4; j++) fma2(acc2[i][j], a2, b2[j]);
            }
        }
        __syncthreads();
    }
#pragma unroll
    for (int i = 0; i < 8; i++) {
        int m = bm + tm + i;
        if (m >= M) continue;
#pragma unroll
        for (int j = 0; j < 4; j++) {
            float2 f = upk2(acc2[i][j]);
            int n = bn + tn + 2 * j;
            if (n < N)     C[(size_t)m * N + n]     = f.x;
            if (n + 1 < N) C[(size_t)m * N + n + 1] = f.y;
        }
    }
}

// =====================================================================
// bf16x6 emulated-fp32 tensor-core GEMM (value path only; smooth effect)
// C[M,N] = A[M,K]*B[N,K]^T. M%128==0, N%64==0, K%16==0.
// =====================================================================
__device__ __forceinline__ void split_pack(float x, float y,
                                           unsigned &ph, unsigned &pm, unsigned &pl)
{
    __nv_bfloat16 hx = __float2bfloat16(x);
    float rx  = x - __bfloat162float(hx);
    __nv_bfloat16 mx = __float2bfloat16(rx);
    float r2x = rx - __bfloat162float(mx);
    __nv_bfloat16 lx = __float2bfloat16(r2x);
    __nv_bfloat16 hy = __float2bfloat16(y);
    float ry  = y - __bfloat162float(hy);
    __nv_bfloat16 my = __float2bfloat16(ry);
    float r2y = ry - __bfloat162float(my);
    __nv_bfloat16 ly = __float2bfloat16(r2y);
    ph = (unsigned)__bfloat16_as_ushort(hx) | ((unsigned)__bfloat16_as_ushort(hy) << 16);
    pm = (unsigned)__bfloat16_as_ushort(mx) | ((unsigned)__bfloat16_as_ushort(my) << 16);
    pl = (unsigned)__bfloat16_as_ushort(lx) | ((unsigned)__bfloat16_as_ushort(ly) << 16);
}

#define MMA_BF16(cc, aa, bb)                                                     \
    asm volatile(                                                                \
        "mma.sync.aligned.m16n8k16.row.col.f32.bf16.bf16.f32 "                   \
        "{%0,%1,%2,%3},{%4,%5,%6,%7},{%8,%9},{%0,%1,%2,%3};\n"                   \
        : "+f"((cc)[0]), "+f"((cc)[1]), "+f"((cc)[2]), "+f"((cc)[3])             \
        : "r"((aa)[0]), "r"((aa)[1]), "r"((aa)[2]), "r"((aa)[3]),                \
          "r"((bb)[0]), "r"((bb)[1]))

__global__ __launch_bounds__(256) void gemm_bf16x6(
    const float* __restrict__ A, const float* __restrict__ B, float* __restrict__ C,
    int M, int N, int K)
{
    __shared__ uint4 As4[3][2][128];
    __shared__ uint2 Bs2[3][2][64][2];
    const int bm = blockIdx.y * 128, bn = blockIdx.x * 64;
    const int tid = threadIdx.x, lane = tid & 31, warp = tid >> 5;
    const int wm0 = (warp >> 1) * 32, wn0 = (warp & 1) * 32;
    const int fr = lane >> 2, fc = lane & 3;
    const int arow = tid >> 1, ahalf = tid & 1;
    const int brow = tid >> 2, bq = tid & 3;
    const float* Aptr = A + (size_t)(bm + arow) * K + ahalf * 8;
    const float* Bptr = B + (size_t)(bn + brow) * K + bq * 4;
    const unsigned* Aw = (const unsigned*)As4;
    const unsigned* Bw = (const unsigned*)Bs2;

    float acc[2][4][4];
#pragma unroll
    for (int a = 0; a < 2; a++)
#pragma unroll
        for (int b = 0; b < 4; b++)
#pragma unroll
            for (int c = 0; c < 4; c++) acc[a][b][c] = 0.f;

    for (int k0 = 0; k0 < K; k0 += 16) {
        __syncthreads();
        {
            float4 f0 = *(const float4*)(Aptr + k0);
            float4 f1 = *(const float4*)(Aptr + k0 + 4);
            unsigned h0,h1,h2,h3, m0,m1,m2,m3, l0,l1,l2,l3;
            split_pack(f0.x, f0.y, h0, m0, l0);
            split_pack(f0.z, f0.w, h1, m1, l1);
            split_pack(f1.x, f1.y, h2, m2, l2);
            split_pack(f1.z, f1.w, h3, m3, l3);
            As4[0][ahalf][arow] = make_uint4(h0, h1, h2, h3);
            As4[1][ahalf][arow] = make_uint4(m0, m1, m2, m3);
            As4[2][ahalf][arow] = make_uint4(l0, l1, l2, l3);
        }
        {
            float4 f0 = *(const float4*)(Bptr + k0);
            unsigned bh0, bh1, bm0, bm1, bl0, bl1;
            split_pack(f0.x, f0.y, bh0, bm0, bl0);
            split_pack(f0.z, f0.w, bh1, bm1, bl1);
            Bs2[0][bq >> 1][brow][bq & 1] = make_uint2(bh0, bh1);
            Bs2[1][bq >> 1][brow][bq & 1] = make_uint2(bm0, bm1);
            Bs2[2][bq >> 1][brow][bq & 1] = make_uint2(bl0, bl1);
        }
        __syncthreads();

        unsigned bfr[4][3][2];
#pragma unroll
        for (int ni = 0; ni < 4; ni++) {
            int rowb = wn0 + ni * 8 + fr;
#pragma unroll
            for (int s = 0; s < 3; s++) {
                bfr[ni][s][0] = Bw[((s * 2 + 0) * 64 + rowb) * 4 + fc];
                bfr[ni][s][1] = Bw[((s * 2 + 1) * 64 + rowb) * 4 + fc];
            }
        }
#pragma unroll
        for (int mi = 0; mi < 2; mi++) {
            unsigned afr[3][4];
            int ra = wm0 + mi * 16;
#pragma unroll
            for (int s = 0; s < 3; s++) {
                afr[s][0] = Aw[((s * 2 + 0) * 128 + ra + fr)     * 4 + fc];
                afr[s][1] = Aw[((s * 2 + 0) * 128 + ra + 8 + fr) * 4 + fc];
                afr[s][2] = Aw[((s * 2 + 1) * 128 + ra + fr)     * 4 + fc];
                afr[s][3] = Aw[((s * 2 + 1) * 128 + ra + 8 + fr) * 4 + fc];
            }
#pragma unroll
            for (int ni = 0; ni < 4; ni++) {
                MMA_BF16(acc[mi][ni], afr[0], bfr[ni][0]);  // hh
                MMA_BF16(acc[mi][ni], afr[0], bfr[ni][1]);  // h*m
                MMA_BF16(acc[mi][ni], afr[1], bfr[ni][0]);  // m*h
                MMA_BF16(acc[mi][ni], afr[1], bfr[ni][1]);  // m*m
                MMA_BF16(acc[mi][ni], afr[0], bfr[ni][2]);  // h*l
                MMA_BF16(acc[mi][ni], afr[2], bfr[ni][0]);  // l*h
            }
        }
    }
#pragma unroll
    for (int mi = 0; mi < 2; mi++)
#pragma unroll
        for (int ni = 0; ni < 4; ni++) {
            int row = bm + wm0 + mi * 16 + fr;
            int col = bn + wn0 + ni * 8 + 2 * fc;
            *(float2*)(C + (size_t)row * N + col)       = make_float2(acc[mi][ni][0], acc[mi][ni][1]);
            *(float2*)(C + (size_t)(row + 8) * N + col) = make_float2(acc[mi][ni][2], acc[mi][ni][3]);
        }
}

// ---------------- warp-per-output GEMM (ki N=128, wts N=32) — baseline-identical ----------------
__global__ void gemm_warpdot(const float* __restrict__ A, const float* __restrict__ B,
                             float* __restrict__ C, int M, int N, int K, float scale)
{
    int gw = (int)((blockIdx.x * (size_t)blockDim.x + threadIdx.x) >> 5);
    int lane = threadIdx.x & 31;
    if (gw >= M * N) return;
    int m = gw / N, n = gw % N;
    const float* a = A + (size_t)m * K;
    const float* b = B + (size_t)n * K;
    float s = 0.f;
    for (int k = lane * 4; k < K; k += 128) {
        float4 va = *(const float4*)(a + k);
        float4 vb = *(const float4*)(b + k);
        s += va.x * vb.x + va.y * vb.y + va.z * vb.z + va.w * vb.w;
    }
#pragma unroll
    for (int o = 16; o; o >>= 1) s += __shfl_xor_sync(0xffffffffu, s, o);
    if (lane == 0) C[(size_t)m * N + n] = s * scale;
}

// ---------------- row rmsnorm ----------------
__global__ void rmsnorm_kernel(const float* __restrict__ in, const float* __restrict__ w,
                               float* __restrict__ out, int cols, int in_stride, int out_stride,
                               float eps)
{
    int row = blockIdx.x;
    const float* x = in + (size_t)row * in_stride;
    float* y = out + (size_t)row * out_stride;
    float ss = 0.f;
    for (int i = threadIdx.x; i < cols; i += blockDim.x) { float v = x[i]; ss += v * v; }
    __shared__ float red[32];
    int lane = threadIdx.x & 31, wp = threadIdx.x >> 5;
#pragma unroll
    for (int o = 16; o; o >>= 1) ss += __shfl_xor_sync(0xffffffffu, ss, o);
    if (lane == 0) red[wp] = ss;
    __syncthreads();
    int nw = blockDim.x >> 5;
    float tot = 0.f;
    for (int i = 0; i < nw; i++) tot += red[i];
    float inv = rsqrtf(tot / (float)cols + eps);
    for (int i = threadIdx.x; i < cols; i += blockDim.x) y[i] = x[i] * inv * w[i];
}

// ---------------- layernorm (128 cols) ----------------
__global__ void layernorm128_kernel(float* __restrict__ x, const float* __restrict__ w,
                                    const float* __restrict__ b)
{
    int row = blockIdx.x;
    float* p = x + (size_t)row * DIi;
    int tid = threadIdx.x, lane = tid & 31, wp = tid >> 5;
    float v = p[tid];
    __shared__ float red[4];
    float t = v;
#pragma unroll
    for (int o = 16; o; o >>= 1) t += __shfl_xor_sync(0xffffffffu, t, o);
    if (lane == 0) red[wp] = t;
    __syncthreads();
    float mean = (red[0] + red[1] + red[2] + red[3]) * (1.f / 128.f);
    __syncthreads();
    float d = v - mean;
    t = d * d;
#pragma unroll
    for (int o = 16; o; o >>= 1) t += __shfl_xor_sync(0xffffffffu, t, o);
    if (lane == 0) red[wp] = t;
    __syncthreads();
    float var = (red[0] + red[1] + red[2] + red[3]) * (1.f / 128.f);
    p[tid] = d * rsqrtf(var + 1e-5f) * w[tid] + b[tid];
}

// ---------------- rope kernels ----------------
__global__ void rope_inter_q(float* __restrict__ q, const float* __restrict__ c,
                             const float* __restrict__ sn)
{
    int n = blockIdx.x * blockDim.x + threadIdx.x;
    if (n >= SQ * H * 32) return;
    int s = n / (H * 32); int r = n % (H * 32); int h = r / 32; int i = r % 32;
    float* p = q + (size_t)s * (H * DQK) + h * DQK + DN + 2 * i;
    float x0 = p[0], x1 = p[1];
    float cc = c[s * 32 + i], ss = sn[s * 32 + i];
    p[0] = x0 * cc - x1 * ss;
    p[1] = x0 * ss + x1 * cc;
}

__global__ void rope_inter_kpe(const float* __restrict__ kvall, const float* __restrict__ c,
                               const float* __restrict__ sn, float* __restrict__ kpe)
{
    int n = blockIdx.x * blockDim.x + threadIdx.x;
    if (n >= SQ * 32) return;
    int s = n / 32, i = n % 32;
    const float* p = kvall + (size_t)s * (KRr + DRR) + KRr + 2 * i;
    float x0 = p[0], x1 = p[1];
    float cc = c[s * 32 + i], ss = sn[s * 32 + i];
    kpe[(size_t)s * DRR + 2 * i]     = x0 * cc - x1 * ss;
    kpe[(size_t)s * DRR + 2 * i + 1] = x0 * ss + x1 * cc;
}

__global__ void rope_half_qi_kernel(float* __restrict__ qi, const float* __restrict__ c,
                                    const float* __restrict__ sn)
{
    int n = blockIdx.x * blockDim.x + threadIdx.x;
    if (n >= SQ * HIi * 32) return;
    int s = n / (HIi * 32); int r = n % (HIi * 32); int h = r / 32; int i = r % 32;
    float* p = qi + (size_t)s * (HIi * DIi) + h * DIi;
    float x0 = p[i], x1 = p[i + 32];
    float cc = c[s * 32 + i], ss = sn[s * 32 + i];
    p[i]      = x0 * cc - x1 * ss;
    p[i + 32] = x0 * ss + x1 * cc;
}

__global__ void rope_half_ki_kernel(float* __restrict__ ki, const float* __restrict__ c,
                                    const float* __restrict__ sn)
{
    int n = blockIdx.x * blockDim.x + threadIdx.x;
    if (n >= SQ * 32) return;
    int s = n / 32, i = n % 32;
    float* p = ki + (size_t)s * DIi;
    float x0 = p[i], x1 = p[i + 32];
    float cc = c[s * 32 + i], ss = sn[s * 32 + i];
    p[i]      = x0 * cc - x1 * ss;
    p[i + 32] = x0 * ss + x1 * cc;
}

// ---------------- pack k / v ----------------
__global__ void pack_k_kernel(const float* __restrict__ kvp, const float* __restrict__ kpe,
                              float* __restrict__ k)
{
    int n = blockIdx.x * blockDim.x + threadIdx.x;
    if (n >= SQ * H * DQK) return;
    int s = n / (H * DQK); int r = n % (H * DQK); int h = r / DQK; int d = r % DQK;
    k[n] = (d < DN) ? kvp[(size_t)s * (H * (DN + DV)) + h * (DN + DV) + d]
                    : kpe[(size_t)s * DRR + (d - DN)];
}

__global__ void pack_v_kernel(const float* __restrict__ kvp, float* __restrict__ v)
{
    int n = blockIdx.x * blockDim.x + threadIdx.x;
    if (n >= SQ * H * DV) return;
    int s = n / (H * DV); int r = n % (H * DV); int h = r / DV; int d = r % DV;
    v[n] = kvp[(size_t)s * (H * (DN + DV)) + h * (DN + DV) + DN + d];
}

// =====================================================================
// indexer v2: 64x64 tile, 4x4 register blocking, fp32x2 FFMA2.
// Accumulation order per output element identical to round-0 kernel
// (dd = 0..127 sequential, then relu*w accumulated over h sequential)
// -> bit-identical iscore -> identical top-k selections.
// =====================================================================
__global__ __launch_bounds__(256) void indexer_kernel(
    const float* __restrict__ qi, const float* __restrict__ ki,
    const float* __restrict__ wts, float* __restrict__ iscore)
{
    int t0 = blockIdx.x * 64, s0 = blockIdx.y * 64;
    if (t0 > s0 + 63) return;
    extern __shared__ float dyn[];
    float* kst = dyn;                    // [128][68] k transposed
    float* qs  = dyn + 128 * 68;         // [64][132]
    float* ws  = qs + 64 * 132;          // [64][33]
    int tid = threadIdx.x;

#pragma unroll
    for (int i = 0; i < 8; i++) {
        int lin = i * 256 + tid;
        int t = lin >> 5, dq = (lin & 31) * 4;
        float4 kv = *(const float4*)(ki + (size_t)(t0 + t) * DIi + dq);
        kst[(dq + 0) * 68 + t] = kv.x;
        kst[(dq + 1) * 68 + t] = kv.y;
        kst[(dq + 2) * 68 + t] = kv.z;
        kst[(dq + 3) * 68 + t] = kv.w;
    }
    {
        int s = tid >> 2, hg = (tid & 3) * 8;
        float4 w0 = *(const float4*)(wts + (size_t)(s0 + s) * HIi + hg);
        float4 w1 = *(const float4*)(wts + (size_t)(s0 + s) * HIi + hg + 4);
        float* wp = ws + s * 33 + hg;
        wp[0] = w0.x; wp[1] = w0.y; wp[2] = w0.z; wp[3] = w0.w;
        wp[4] = w1.x; wp[5] = w1.y; wp[6] = w1.z; wp[7] = w1.w;
    }

    int si = (tid >> 4) * 4, ti = (tid & 15) * 4;
    int qls = tid >> 2, qld = (tid & 3) * 32;
    float score[4][4];
#pragma unroll
    for (int i = 0; i < 4; i++)
#pragma unroll
        for (int j = 0; j < 4; j++) score[i][j] = 0.f;

    for (int h = 0; h < HIi; h++) {
        __syncthreads();
        const float* qp = qi + (size_t)(s0 + qls) * (HIi * DIi) + h * DIi + qld;
#pragma unroll
        for (int j = 0; j < 8; j++) {
            float4 qv = *(const float4*)(qp + j * 4);
            *(float4*)&qs[qls * 132 + qld + j * 4] = qv;
        }
        __syncthreads();
        unsigned long long dot2[4][2];
#pragma unroll
        for (int i = 0; i < 4; i++) { dot2[i][0] = 0ULL; dot2[i][1] = 0ULL; }
#pragma unroll 8
        for (int dd = 0; dd < DIi; dd++) {
            float4 kv = *(const float4*)&kst[dd * 68 + ti];
            unsigned long long k01 = pk2(kv.x, kv.y);
            unsigned long long k23 = pk2(kv.z, kv.w);
#pragma unroll
            for (int i = 0; i < 4; i++) {
                float qv = qs[(si + i) * 132 + dd];
                unsigned long long q2 = pk2(qv, qv);
                fma2(dot2[i][0], q2, k01);
                fma2(dot2[i][1], q2, k23);
            }
        }
#pragma unroll
        for (int i = 0; i < 4; i++) {
            float wv = ws[(si + i) * 33 + h];
            float2 d01 = upk2(dot2[i][0]);
            float2 d23 = upk2(dot2[i][1]);
            score[i][0] += fmaxf(d01.x * INV_SQRT_DI, 0.f) * wv;
            score[i][1] += fmaxf(d01.y * INV_SQRT_DI, 0.f) * wv;
            score[i][2] += fmaxf(d23.x * INV_SQRT_DI, 0.f) * wv;
            score[i][3] += fmaxf(d23.y * INV_SQRT_DI, 0.f) * wv;
        }
    }
#pragma unroll
    for (int i = 0; i < 4; i++) {
        int s = s0 + si + i;
#pragma unroll
        for (int j = 0; j < 4; j++) {
            int t = t0 + ti + j;
            if (t <= s) iscore[(size_t)s * SQ + t] = score[i][j];
        }
    }
}

// ---------------- exact top-512: radix select + fully parallel ordered fill ----------------
__device__ __forceinline__ unsigned forder(float f)
{
    unsigned u = __float_as_uint(f);
    return (u & 0x80000000u) ? ~u : (u | 0x80000000u);
}

__global__ __launch_bounds__(256) void topk_kernel(const float* __restrict__ iscore,
                                                   int* __restrict__ tidx, int* __restrict__ tcnt)
{
    int s = blockIdx.x;
    int n = s + 1;
    int tid = threadIdx.x;
    const float* row = iscore + (size_t)s * SQ;
    int* out = tidx + (size_t)s * TOPK;
    if (n <= TOPK) {
        for (int t = tid; t < n; t += 256) out[t] = t;
        if (tid == 0) tcnt[s] = n;
        return;
    }
    __shared__ int hist[256];
    __shared__ unsigned s_pref;
    __shared__ int s_k;
    __shared__ int sc[256];
    if (tid == 0) { s_pref = 0u; s_k = TOPK; }
    __syncthreads();
    for (int pass = 0; pass < 4; pass++) {
        int sh = 24 - 8 * pass;
        unsigned hmask = (pass == 0) ? 0u : (0xFFFFFFFFu << (sh + 8));
        hist[tid] = 0;
        __syncthreads();
        unsigned pref = s_pref;
        for (int t = tid; t < n; t += 256) {
            unsigned u = forder(row[t]);
            if ((u & hmask) == pref) atomicAdd(&hist[(u >> sh) & 255u], 1);
        }
        __syncthreads();
        if (tid == 0) {
            int k = s_k, c = 0, j = 255;
            for (; j >= 0; j--) {
                if (c + hist[j] >= k) break;
                c += hist[j];
            }
            s_k = k - c;
            s_pref = s_pref | ((unsigned)j << sh);
        }
        __syncthreads();
    }
    unsigned uthr = s_pref;
    int kneed = s_k;
    int chunk = (n + 255) / 256;
    int beg = tid * chunk;
    int end = beg + chunk; if (end > n) end = n;
    int cntg = 0, cnte = 0;
    for (int t = beg; t < end; t++) {
        unsigned u = forder(row[t]);
        if (u > uthr) cntg++;
        else if (u == uthr) cnte++;
    }
    sc[tid] = cntg;
    __syncthreads();
    for (int o = 1; o < 256; o <<= 1) {
        int v = (tid >= o) ? sc[tid - o] : 0;
        __syncthreads();
        sc[tid] += v;
        __syncthreads();
    }
    int offg = sc[tid] - cntg;
    int totalg = sc[255];
    __syncthreads();
    sc[tid] = cnte;
    __syncthreads();
    for (int o = 1; o < 256; o <<= 1) {
        int v = (tid >= o) ? sc[tid - o] : 0;
        __syncthreads();
        sc[tid] += v;
        __syncthreads();
    }
    int offe = sc[tid] - cnte;
    for (int t = beg; t < end; t++) {
        unsigned u = forder(row[t]);
        if (u > uthr) {
            out[offg++] = t;
        } else if (u == uthr) {
            int rank = offe++;
            if (rank < kneed) out[totalg + rank] = t;  // ties: lowest t first
        }
    }
    if (tid == 0) tcnt[s] = TOPK;
}

// ---------------- sparse attention per (s, h) ----------------
__global__ __launch_bounds__(256) void attn_kernel(
    const float* __restrict__ q, const float* __restrict__ k, const float* __restrict__ v,
    const int* __restrict__ tidx, const int* __restrict__ tcnt, float* __restrict__ out)
{
    int s = blockIdx.x, h = blockIdx.y;
    int tid = threadIdx.x, lane = tid & 31, wp = tid >> 5;
    int n = tcnt[s];
    __shared__ float qs[DQK];
    __shared__ float lg[TOPK];
    __shared__ int   ix[TOPK];
    __shared__ float red[8];
    __shared__ float accs[128];
    if (tid < DQK) qs[tid] = q[(size_t)s * (H * DQK) + h * DQK + tid];
    for (int j = tid; j < n; j += 256) ix[j] = tidx[(size_t)s * TOPK + j];
    __syncthreads();
    for (int j = wp; j < n; j += 8) {
        const float* kp = k + (size_t)ix[j] * (H * DQK) + h * DQK;
        float d = 0.f;
#pragma unroll
        for (int c = 0; c < DQK / 32; c++) d += qs[lane + c * 32] * kp[lane + c * 32];
#pragma unroll
        for (int o = 16; o; o >>= 1) d += __shfl_xor_sync(0xffffffffu, d, o);
        if (lane == 0) lg[j] = d * INV_SQRT_DQK;
    }
    __syncthreads();
    float m = -FLT_MAX;
    for (int j = tid; j < n; j += 256) m = fmaxf(m, lg[j]);
#pragma unroll
    for (int o = 16; o; o >>= 1) m = fmaxf(m, __shfl_xor_sync(0xffffffffu, m, o));
    if (lane == 0) red[wp] = m;
    __syncthreads();
    m = red[0];
#pragma unroll
    for (int i = 1; i < 8; i++) m = fmaxf(m, red[i]);
    __syncthreads();
    float ssum = 0.f;
    for (int j = tid; j < n; j += 256) { float e = __expf(lg[j] - m); lg[j] = e; ssum += e; }
#pragma unroll
    for (int o = 16; o; o >>= 1) ssum += __shfl_xor_sync(0xffffffffu, ssum, o);
    if (lane == 0) red[wp] = ssum;
    __syncthreads();
    float tot = 0.f;
#pragma unroll
    for (int i = 0; i < 8; i++) tot += red[i];
    float inv = 1.f / tot;
    int d = tid & 127, half = tid >> 7;
    float acc = 0.f;
#pragma unroll 4
    for (int j = half; j < n; j += 2)
        acc += lg[j] * v[(size_t)ix[j] * (H * DV) + h * DV + d];
    if (half == 1) accs[d] = acc;
    __syncthreads();
    if (half == 0)
        out[(size_t)s * (H * DV) + h * DV + d] = (acc + accs[d]) * inv;
}

// ---------------- host launcher ----------------
extern "C" void kernel_launch(void* const* d_in, const int* in_sizes, int n_in,
                              void* d_out, int out_size)
{
    const float *hidden, *cosp, *sinp, *wq_a, *q_norm_w, *wq_b, *wkv_a, *kv_norm_w,
                *wkv_b, *wo, *idx_wq_b, *idx_wk, *idx_kn_w, *idx_kn_b, *idx_wproj;
    if (n_in >= 2 && in_sizes[1] == 3145728) {
        hidden    = (const float*)d_in[0];
        wq_a      = (const float*)d_in[1];
        q_norm_w  = (const float*)d_in[2];
        wq_b      = (const float*)d_in[3];
        wkv_a     = (const float*)d_in[4];
        kv_norm_w = (const float*)d_in[5];
        wkv_b     = (const float*)d_in[6];
        wo        = (const float*)d_in[7];
        idx_wq_b  = (const float*)d_in[8];
        idx_wk    = (const float*)d_in[9];
        idx_kn_w  = (const float*)d_in[10];
        idx_kn_b  = (const float*)d_in[11];
        idx_wproj = (const float*)d_in[12];
        cosp      = (const float*)d_in[13];
        sinp      = (const float*)d_in[14];
    } else {
        hidden    = (const float*)d_in[0];
        cosp      = (const float*)d_in[1];
        sinp      = (const float*)d_in[2];
        wq_a      = (const float*)d_in[4];
        q_norm_w  = (const float*)d_in[5];
        wq_b      = (const float*)d_in[6];
        wkv_a     = (const float*)d_in[7];
        kv_norm_w = (const float*)d_in[8];
        wkv_b     = (const float*)d_in[9];
        wo        = (const float*)d_in[10];
        idx_wq_b  = (const float*)d_in[11];
        idx_wk    = (const float*)d_in[12];
        idx_kn_w  = (const float*)d_in[13];
        idx_kn_b  = (const float*)d_in[14];
        idx_wproj = (const float*)d_in[15];
    }

    float *qr, *q, *kvall, *kv, *kpe, *kvp, *k, *v, *qi, *ki, *wtsb, *iscore, *attnb;
    int *tix, *tcn;
    cudaGetSymbolAddress((void**)&qr,    g_qr);
    cudaGetSymbolAddress((void**)&q,     g_q);
    cudaGetSymbolAddress((void**)&kvall, g_kvall);
    cudaGetSymbolAddress((void**)&kv,    g_kv);
    cudaGetSymbolAddress((void**)&kpe,   g_kpe);
    cudaGetSymbolAddress((void**)&kvp,   g_kvp);
    cudaGetSymbolAddress((void**)&k,     g_k);
    cudaGetSymbolAddress((void**)&v,     g_v);
    cudaGetSymbolAddress((void**)&qi,    g_qi);
    cudaGetSymbolAddress((void**)&ki,    g_ki);
    cudaGetSymbolAddress((void**)&wtsb,  g_wts);
    cudaGetSymbolAddress((void**)&iscore,g_iscore);
    cudaGetSymbolAddress((void**)&attnb, g_attn);
    cudaGetSymbolAddress((void**)&tix,   g_tidx);
    cudaGetSymbolAddress((void**)&tcn,   g_tcnt);

    const int ISMEM = (128 * 68 + 64 * 132 + 64 * 33) * 4;   // 77056 B
    cudaFuncSetAttribute(indexer_kernel, cudaFuncAttributeMaxDynamicSharedMemorySize, ISMEM);

    // ---- indexer-critical path (bit-identical to the passing fp32 baseline) ----
    // 1. qr = rmsnorm(hidden @ wq_a.T)   [feeds qi -> iscore -> top-k]
    sgemm_nt<<<dim3(16, 12), 256>>>(hidden, wq_a, qr, SQ, QRr, DM);
    rmsnorm_kernel<<<SQ, 256>>>(qr, q_norm_w, qr, QRr, QRr, QRr, 1e-6f);

    // 5. qi = rope_half(qr @ idx_wq_b.T)
    sgemm_nt<<<dim3(16, 32), 256>>>(qr, idx_wq_b, qi, SQ, HIi * DIi, QRr);
    rope_half_qi_kernel<<<(SQ * HIi * 32 + 255) / 256, 256>>>(qi, cosp, sinp);

    // 6. ki = rope_half(layernorm(hidden @ idx_wk.T))
    gemm_warpdot<<<(SQ * DIi * 32) / 256, 256>>>(hidden, idx_wk, ki, SQ, DIi, DM, 1.f);
    layernorm128_kernel<<<SQ, 128>>>(ki, idx_kn_w, idx_kn_b);
    rope_half_ki_kernel<<<(SQ * 32 + 255) / 256, 256>>>(ki, cosp, sinp);

    // 7. wts = hidden @ idx_wproj.T * HI^-0.5
    gemm_warpdot<<<(SQ * HIi * 32) / 256, 256>>>(hidden, idx_wproj, wtsb, SQ, HIi, DM, INV_SQRT_HI);

    // ---- value path (smooth; bf16x6 tensor cores) ----
    // 2. q = rope(qr @ wq_b.T)
    gemm_bf16x6<<<dim3((H * DQK) / 64, 16), 256>>>(qr, wq_b, q, SQ, H * DQK, QRr);
    rope_inter_q<<<(SQ * H * 32 + 255) / 256, 256>>>(q, cosp, sinp);

    // 3. kv_all = hidden @ wkv_a.T ; kv = rmsnorm ; kpe = rope
    gemm_bf16x6<<<dim3((KRr + DRR) / 64, 16), 256>>>(hidden, wkv_a, kvall, SQ, KRr + DRR, DM);
    rmsnorm_kernel<<<SQ, 256>>>(kvall, kv_norm_w, kv, KRr, KRr + DRR, KRr, 1e-6f);
    rope_inter_kpe<<<(SQ * 32 + 255) / 256, 256>>>(kvall, cosp, sinp, kpe);

    // 4. kvp = kv @ wkv_b.T ; split k/v
    gemm_bf16x6<<<dim3((H * (DN + DV)) / 64, 16), 256>>>(kv, wkv_b, kvp, SQ, H * (DN + DV), KRr);
    pack_k_kernel<<<(SQ * H * DQK + 255) / 256, 256>>>(kvp, kpe, k);
    pack_v_kernel<<<(SQ * H * DV + 255) / 256, 256>>>(kvp, v);

    // 8. indexer scores (causal)
    indexer_kernel<<<dim3(32, 32), 256, ISMEM>>>(qi, ki, wtsb, iscore);

    // 9. exact top-512 per row
    topk_kernel<<<SQ, 256>>>(iscore, tix, tcn);

    // 10. sparse attention
    attn_kernel<<<dim3(SQ, H), 256>>>(q, k, v, tix, tcn, attnb);

    // 11. output projection
    gemm_bf16x6<<<dim3(DM / 64, 16), 256>>>(attnb, wo, (float*)d_out, SQ, DM, DM);
}

// round 6
// speedup vs baseline: 1.2940x; 1.0004x over previous
#include <cuda_runtime.h>
#include <cuda_bf16.h>
#include <math.h>
#include <float.h>
#include <stdint.h>

// ---------------- problem constants ----------------
#define SQ   2048
#define DM   2048
#define H    16
#define DN   128
#define DRR  64
#define DV   128
#define QRr  1536
#define KRr  512
#define HIi  32
#define DIi  128
#define TOPK 512
#define DQK  192

#define INV_SQRT_DQK 0.07216878364870322f
#define INV_SQRT_DI  0.08838834764831845f
#define INV_SQRT_HI  0.17677669529663687f

// ---------------- scratch ----------------
__device__ float g_qr   [SQ * QRr];
__device__ float g_q    [SQ * H * DQK];
__device__ float g_kvall[SQ * (KRr + DRR)];
__device__ float g_kv   [SQ * KRr];
__device__ float g_kpe  [SQ * DRR];
__device__ float g_kvp  [SQ * H * (DN + DV)];
__device__ float g_k    [SQ * H * DQK];
__device__ float g_v    [SQ * H * DV];
__device__ float g_qi   [SQ * HIi * DIi];
__device__ float g_ki   [SQ * DIi];
__device__ float g_wts  [SQ * HIi];
__device__ float g_iscore[(size_t)SQ * SQ];
__device__ int   g_tidx [SQ * TOPK];
__device__ int   g_tcnt [SQ];
__device__ float g_attn [SQ * H * DV];

// ---------------- packed fp32x2 FMA helpers (exact fp32 RN per lane) ----------------
__device__ __forceinline__ unsigned long long pk2(float x, float y)
{
    unsigned long long r;
    asm("mov.b64 %0, {%1, %2};" : "=l"(r) : "f"(x), "f"(y));
    return r;
}
__device__ __forceinline__ void fma2(unsigned long long &c, unsigned long long a, unsigned long long b)
{
    asm("fma.rn.f32x2 %0, %1, %2, %0;" : "+l"(c) : "l"(a), "l"(b));
}
__device__ __forceinline__ float2 upk2(unsigned long long v)
{
    float2 f;
    asm("mov.b64 {%0, %1}, %2;" : "=f"(f.x), "=f"(f.y) : "l"(v));
    return f;
}

// ---------------- SGEMM (C[M,N]=A[M,K]*B[N,K]^T), 128x128x16, fp32x2 FFMA2 ----------------
// Per-element accumulation order identical to the scalar fp32 baseline:
// each acc[i][j] is its own RN-FMA chain over k=0..K-1 in order -> bit-identical.
__global__ __launch_bounds__(256) void sgemm_nt(
    const float* __restrict__ A, const float* __restrict__ B, float* __restrict__ C,
    int M, int N, int K)
{
    __shared__ float As[16][128];
    __shared__ float Bs[16][128];
    const int bm = blockIdx.x * 128, bn = blockIdx.y * 128;
    const int tid = threadIdx.x;
    const int lr = tid >> 2;
    const int lc = (tid & 3) << 2;
    const int tm = (tid >> 4) << 3;
    const int tn = (tid & 15) << 3;
    unsigned long long acc2[8][4];
#pragma unroll
    for (int i = 0; i < 8; i++)
#pragma unroll
        for (int j = 0; j < 4; j++) acc2[i][j] = 0ULL;

    for (int k0 = 0; k0 < K; k0 += 16) {
#pragma unroll
        for (int i = 0; i < 2; i++) {
            int r = lr + i * 64;
            float4 va = make_float4(0.f, 0.f, 0.f, 0.f);
            float4 vb = make_float4(0.f, 0.f, 0.f, 0.f);
            if (bm + r < M) va = *(const float4*)(A + (size_t)(bm + r) * K + k0 + lc);
            if (bn + r < N) vb = *(const float4*)(B + (size_t)(bn + r) * K + k0 + lc);
            As[lc + 0][r] = va.x; As[lc + 1][r] = va.y; As[lc + 2][r] = va.z; As[lc + 3][r] = va.w;
            Bs[lc + 0][r] = vb.x; Bs[lc + 1][r] = vb.y; Bs[lc + 2][r] = vb.z; Bs[lc + 3][r] = vb.w;
        }
        __syncthreads();
#pragma unroll
        for (int kk = 0; kk < 16; kk++) {
            float a[8], b[8];
#pragma unroll
            for (int i = 0; i < 8; i++) a[i] = As[kk][tm + i];
#pragma unroll
            for (int j = 0; j < 8; j++) b[j] = Bs[kk][tn + j];
            unsigned long long b2[4];
#pragma unroll
            for (int j = 0; j < 4; j++) b2[j] = pk2(b[2 * j], b[2 * j + 1]);
#pragma unroll
            for (int i = 0; i < 8; i++) {
                unsigned long long a2 = pk2(a[i], a[i]);
#pragma unroll
                for (int j = 0; j < 4; j++) fma2(acc2[i][j], a2, b2[j]);
            }
        }
        __syncthreads();
    }
#pragma unroll
    for (int i = 0; i < 8; i++) {
        int m = bm + tm + i;
        if (m >= M) continue;
#pragma unroll
        for (int j = 0; j < 4; j++) {
            float2 f = upk2(acc2[i][j]);
            int n = bn + tn + 2 * j;
            if (n < N)     C[(size_t)m * N + n]     = f.x;
            if (n + 1 < N) C[(size_t)m * N + n + 1] = f.y;
        }
    }
}

// =====================================================================
// bf16x6 emulated-fp32 tensor-core GEMM (value path only; smooth effect)
// C[M,N] = A[M,K]*B[N,K]^T. M%128==0, N%64==0, K%16==0.
// =====================================================================
__device__ __forceinline__ void split_pack(float x, float y,
                                           unsigned &ph, unsigned &pm, unsigned &pl)
{
    __nv_bfloat16 hx = __float2bfloat16(x);
    float rx  = x - __bfloat162float(hx);
    __nv_bfloat16 mx = __float2bfloat16(rx);
    float r2x = rx - __bfloat162float(mx);
    __nv_bfloat16 lx = __float2bfloat16(r2x);
    __nv_bfloat16 hy = __float2bfloat16(y);
    float ry  = y - __bfloat162float(hy);
    __nv_bfloat16 my = __float2bfloat16(ry);
    float r2y = ry - __bfloat162float(my);
    __nv_bfloat16 ly = __float2bfloat16(r2y);
    ph = (unsigned)__bfloat16_as_ushort(hx) | ((unsigned)__bfloat16_as_ushort(hy) << 16);
    pm = (unsigned)__bfloat16_as_ushort(mx) | ((unsigned)__bfloat16_as_ushort(my) << 16);
    pl = (unsigned)__bfloat16_as_ushort(lx) | ((unsigned)__bfloat16_as_ushort(ly) << 16);
}

#define MMA_BF16(cc, aa, bb)                                                     \
    asm volatile(                                                                \
        "mma.sync.aligned.m16n8k16.row.col.f32.bf16.bf16.f32 "                   \
        "{%0,%1,%2,%3},{%4,%5,%6,%7},{%8,%9},{%0,%1,%2,%3};\n"                   \
        : "+f"((cc)[0]), "+f"((cc)[1]), "+f"((cc)[2]), "+f"((cc)[3])             \
        : "r"((aa)[0]), "r"((aa)[1]), "r"((aa)[2]), "r"((aa)[3]),                \
          "r"((bb)[0]), "r"((bb)[1]))

__global__ __launch_bounds__(256) void gemm_bf16x6(
    const float* __restrict__ A, const float* __restrict__ B, float* __restrict__ C,
    int M, int N, int K)
{
    __shared__ uint4 As4[3][2][128];
    __shared__ uint2 Bs2[3][2][64][2];
    const int bm = blockIdx.y * 128, bn = blockIdx.x * 64;
    const int tid = threadIdx.x, lane = tid & 31, warp = tid >> 5;
    const int wm0 = (warp >> 1) * 32, wn0 = (warp & 1) * 32;
    const int fr = lane >> 2, fc = lane & 3;
    const int arow = tid >> 1, ahalf = tid & 1;
    const int brow = tid >> 2, bq = tid & 3;
    const float* Aptr = A + (size_t)(bm + arow) * K + ahalf * 8;
    const float* Bptr = B + (size_t)(bn + brow) * K + bq * 4;
    const unsigned* Aw = (const unsigned*)As4;
    const unsigned* Bw = (const unsigned*)Bs2;

    float acc[2][4][4];
#pragma unroll
    for (int a = 0; a < 2; a++)
#pragma unroll
        for (int b = 0; b < 4; b++)
#pragma unroll
            for (int c = 0; c < 4; c++) acc[a][b][c] = 0.f;

    for (int k0 = 0; k0 < K; k0 += 16) {
        __syncthreads();
        {
            float4 f0 = *(const float4*)(Aptr + k0);
            float4 f1 = *(const float4*)(Aptr + k0 + 4);
            unsigned h0,h1,h2,h3, m0,m1,m2,m3, l0,l1,l2,l3;
            split_pack(f0.x, f0.y, h0, m0, l0);
            split_pack(f0.z, f0.w, h1, m1, l1);
            split_pack(f1.x, f1.y, h2, m2, l2);
            split_pack(f1.z, f1.w, h3, m3, l3);
            As4[0][ahalf][arow] = make_uint4(h0, h1, h2, h3);
            As4[1][ahalf][arow] = make_uint4(m0, m1, m2, m3);
            As4[2][ahalf][arow] = make_uint4(l0, l1, l2, l3);
        }
        {
            float4 f0 = *(const float4*)(Bptr + k0);
            unsigned bh0, bh1, bm0, bm1, bl0, bl1;
            split_pack(f0.x, f0.y, bh0, bm0, bl0);
            split_pack(f0.z, f0.w, bh1, bm1, bl1);
            Bs2[0][bq >> 1][brow][bq & 1] = make_uint2(bh0, bh1);
            Bs2[1][bq >> 1][brow][bq & 1] = make_uint2(bm0, bm1);
            Bs2[2][bq >> 1][brow][bq & 1] = make_uint2(bl0, bl1);
        }
        __syncthreads();

        unsigned bfr[4][3][2];
#pragma unroll
        for (int ni = 0; ni < 4; ni++) {
            int rowb = wn0 + ni * 8 + fr;
#pragma unroll
            for (int s = 0; s < 3; s++) {
                bfr[ni][s][0] = Bw[((s * 2 + 0) * 64 + rowb) * 4 + fc];
                bfr[ni][s][1] = Bw[((s * 2 + 1) * 64 + rowb) * 4 + fc];
            }
        }
#pragma unroll
        for (int mi = 0; mi < 2; mi++) {
            unsigned afr[3][4];
            int ra = wm0 + mi * 16;
#pragma unroll
            for (int s = 0; s < 3; s++) {
                afr[s][0] = Aw[((s * 2 + 0) * 128 + ra + fr)     * 4 + fc];
                afr[s][1] = Aw[((s * 2 + 0) * 128 + ra + 8 + fr) * 4 + fc];
                afr[s][2] = Aw[((s * 2 + 1) * 128 + ra + fr)     * 4 + fc];
                afr[s][3] = Aw[((s * 2 + 1) * 128 + ra + 8 + fr) * 4 + fc];
            }
#pragma unroll
            for (int ni = 0; ni < 4; ni++) {
                MMA_BF16(acc[mi][ni], afr[0], bfr[ni][0]);  // hh
                MMA_BF16(acc[mi][ni], afr[0], bfr[ni][1]);  // h*m
                MMA_BF16(acc[mi][ni], afr[1], bfr[ni][0]);  // m*h
                MMA_BF16(acc[mi][ni], afr[1], bfr[ni][1]);  // m*m
                MMA_BF16(acc[mi][ni], afr[0], bfr[ni][2]);  // h*l
                MMA_BF16(acc[mi][ni], afr[2], bfr[ni][0]);  // l*h
            }
        }
    }
#pragma unroll
    for (int mi = 0; mi < 2; mi++)
#pragma unroll
        for (int ni = 0; ni < 4; ni++) {
            int row = bm + wm0 + mi * 16 + fr;
            int col = bn + wn0 + ni * 8 + 2 * fc;
            *(float2*)(C + (size_t)row * N + col)       = make_float2(acc[mi][ni][0], acc[mi][ni][1]);
            *(float2*)(C + (size_t)(row + 8) * N + col) = make_float2(acc[mi][ni][2], acc[mi][ni][3]);
        }
}

// ---------------- warp-per-output GEMM (ki N=128, wts N=32) — baseline-identical ----------------
__global__ void gemm_warpdot(const float* __restrict__ A, const float* __restrict__ B,
                             float* __restrict__ C, int M, int N, int K, float scale)
{
    int gw = (int)((blockIdx.x * (size_t)blockDim.x + threadIdx.x) >> 5);
    int lane = threadIdx.x & 31;
    if (gw >= M * N) return;
    int m = gw / N, n = gw % N;
    const float* a = A + (size_t)m * K;
    const float* b = B + (size_t)n * K;
    float s = 0.f;
    for (int k = lane * 4; k < K; k += 128) {
        float4 va = *(const float4*)(a + k);
        float4 vb = *(const float4*)(b + k);
        s += va.x * vb.x + va.y * vb.y + va.z * vb.z + va.w * vb.w;
    }
#pragma unroll
    for (int o = 16; o; o >>= 1) s += __shfl_xor_sync(0xffffffffu, s, o);
    if (lane == 0) C[(size_t)m * N + n] = s * scale;
}

// ---------------- row rmsnorm ----------------
__global__ void rmsnorm_kernel(const float* __restrict__ in, const float* __restrict__ w,
                               float* __restrict__ out, int cols, int in_stride, int out_stride,
                               float eps)
{
    int row = blockIdx.x;
    const float* x = in + (size_t)row * in_stride;
    float* y = out + (size_t)row * out_stride;
    float ss = 0.f;
    for (int i = threadIdx.x; i < cols; i += blockDim.x) { float v = x[i]; ss += v * v; }
    __shared__ float red[32];
    int lane = threadIdx.x & 31, wp = threadIdx.x >> 5;
#pragma unroll
    for (int o = 16; o; o >>= 1) ss += __shfl_xor_sync(0xffffffffu, ss, o);
    if (lane == 0) red[wp] = ss;
    __syncthreads();
    int nw = blockDim.x >> 5;
    float tot = 0.f;
    for (int i = 0; i < nw; i++) tot += red[i];
    float inv = rsqrtf(tot / (float)cols + eps);
    for (int i = threadIdx.x; i < cols; i += blockDim.x) y[i] = x[i] * inv * w[i];
}

// ---------------- layernorm (128 cols) ----------------
__global__ void layernorm128_kernel(float* __restrict__ x, const float* __restrict__ w,
                                    const float* __restrict__ b)
{
    int row = blockIdx.x;
    float* p = x + (size_t)row * DIi;
    int tid = threadIdx.x, lane = tid & 31, wp = tid >> 5;
    float v = p[tid];
    __shared__ float red[4];
    float t = v;
#pragma unroll
    for (int o = 16; o; o >>= 1) t += __shfl_xor_sync(0xffffffffu, t, o);
    if (lane == 0) red[wp] = t;
    __syncthreads();
    float mean = (red[0] + red[1] + red[2] + red[3]) * (1.f / 128.f);
    __syncthreads();
    float d = v - mean;
    t = d * d;
#pragma unroll
    for (int o = 16; o; o >>= 1) t += __shfl_xor_sync(0xffffffffu, t, o);
    if (lane == 0) red[wp] = t;
    __syncthreads();
    float var = (red[0] + red[1] + red[2] + red[3]) * (1.f / 128.f);
    p[tid] = d * rsqrtf(var + 1e-5f) * w[tid] + b[tid];
}

// ---------------- rope kernels ----------------
__global__ void rope_inter_q(float* __restrict__ q, const float* __restrict__ c,
                             const float* __restrict__ sn)
{
    int n = blockIdx.x * blockDim.x + threadIdx.x;
    if (n >= SQ * H * 32) return;
    int s = n / (H * 32); int r = n % (H * 32); int h = r / 32; int i = r % 32;
    float* p = q + (size_t)s * (H * DQK) + h * DQK + DN + 2 * i;
    float x0 = p[0], x1 = p[1];
    float cc = c[s * 32 + i], ss = sn[s * 32 + i];
    p[0] = x0 * cc - x1 * ss;
    p[1] = x0 * ss + x1 * cc;
}

__global__ void rope_inter_kpe(const float* __restrict__ kvall, const float* __restrict__ c,
                               const float* __restrict__ sn, float* __restrict__ kpe)
{
    int n = blockIdx.x * blockDim.x + threadIdx.x;
    if (n >= SQ * 32) return;
    int s = n / 32, i = n % 32;
    const float* p = kvall + (size_t)s * (KRr + DRR) + KRr + 2 * i;
    float x0 = p[0], x1 = p[1];
    float cc = c[s * 32 + i], ss = sn[s * 32 + i];
    kpe[(size_t)s * DRR + 2 * i]     = x0 * cc - x1 * ss;
    kpe[(size_t)s * DRR + 2 * i + 1] = x0 * ss + x1 * cc;
}

__global__ void rope_half_qi_kernel(float* __restrict__ qi, const float* __restrict__ c,
                                    const float* __restrict__ sn)
{
    int n = blockIdx.x * blockDim.x + threadIdx.x;
    if (n >= SQ * HIi * 32) return;
    int s = n / (HIi * 32); int r = n % (HIi * 32); int h = r / 32; int i = r % 32;
    float* p = qi + (size_t)s * (HIi * DIi) + h * DIi;
    float x0 = p[i], x1 = p[i + 32];
    float cc = c[s * 32 + i], ss = sn[s * 32 + i];
    p[i]      = x0 * cc - x1 * ss;
    p[i + 32] = x0 * ss + x1 * cc;
}

__global__ void rope_half_ki_kernel(float* __restrict__ ki, const float* __restrict__ c,
                                    const float* __restrict__ sn)
{
    int n = blockIdx.x * blockDim.x + threadIdx.x;
    if (n >= SQ * 32) return;
    int s = n / 32, i = n % 32;
    float* p = ki + (size_t)s * DIi;
    float x0 = p[i], x1 = p[i + 32];
    float cc = c[s * 32 + i], ss = sn[s * 32 + i];
    p[i]      = x0 * cc - x1 * ss;
    p[i + 32] = x0 * ss + x1 * cc;
}

// ---------------- pack k / v ----------------
__global__ void pack_k_kernel(const float* __restrict__ kvp, const float* __restrict__ kpe,
                              float* __restrict__ k)
{
    int n = blockIdx.x * blockDim.x + threadIdx.x;
    if (n >= SQ * H * DQK) return;
    int s = n / (H * DQK); int r = n % (H * DQK); int h = r / DQK; int d = r % DQK;
    k[n] = (d < DN) ? kvp[(size_t)s * (H * (DN + DV)) + h * (DN + DV) + d]
                    : kpe[(size_t)s * DRR + (d - DN)];
}

__global__ void pack_v_kernel(const float* __restrict__ kvp, float* __restrict__ v)
{
    int n = blockIdx.x * blockDim.x + threadIdx.x;
    if (n >= SQ * H * DV) return;
    int s = n / (H * DV); int r = n % (H * DV); int h = r / DV; int d = r % DV;
    v[n] = kvp[(size_t)s * (H * (DN + DV)) + h * (DN + DV) + DN + d];
}

// =====================================================================
// indexer v2: 64x64 tile, 4x4 register blocking, fp32x2 FFMA2.
// Accumulation order per output element identical to round-0 kernel
// (dd = 0..127 sequential, then relu*w accumulated over h sequential)
// -> bit-identical iscore -> identical top-k selections.
// =====================================================================
__global__ __launch_bounds__(256) void indexer_kernel(
    const float* __restrict__ qi, const float* __restrict__ ki,
    const float* __restrict__ wts, float* __restrict__ iscore)
{
    int t0 = blockIdx.x * 64, s0 = blockIdx.y * 64;
    if (t0 > s0 + 63) return;
    extern __shared__ float dyn[];
    float* kst = dyn;                    // [128][68] k transposed
    float* qs  = dyn + 128 * 68;         // [64][132]
    float* ws  = qs + 64 * 132;          // [64][33]
    int tid = threadIdx.x;

#pragma unroll
    for (int i = 0; i < 8; i++) {
        int lin = i * 256 + tid;
        int t = lin >> 5, dq = (lin & 31) * 4;
        float4 kv = *(const float4*)(ki + (size_t)(t0 + t) * DIi + dq);
        kst[(dq + 0) * 68 + t] = kv.x;
        kst[(dq + 1) * 68 + t] = kv.y;
        kst[(dq + 2) * 68 + t] = kv.z;
        kst[(dq + 3) * 68 + t] = kv.w;
    }
    {
        int s = tid >> 2, hg = (tid & 3) * 8;
        float4 w0 = *(const float4*)(wts + (size_t)(s0 + s) * HIi + hg);
        float4 w1 = *(const float4*)(wts + (size_t)(s0 + s) * HIi + hg + 4);
        float* wp = ws + s * 33 + hg;
        wp[0] = w0.x; wp[1] = w0.y; wp[2] = w0.z; wp[3] = w0.w;
        wp[4] = w1.x; wp[5] = w1.y; wp[6] = w1.z; wp[7] = w1.w;
    }

    int si = (tid >> 4) * 4, ti = (tid & 15) * 4;
    int qls = tid >> 2, qld = (tid & 3) * 32;
    float score[4][4];
#pragma unroll
    for (int i = 0; i < 4; i++)
#pragma unroll
        for (int j = 0; j < 4; j++) score[i][j] = 0.f;

    for (int h = 0; h < HIi; h++) {
        __syncthreads();
        const float* qp = qi + (size_t)(s0 + qls) * (HIi * DIi) + h * DIi + qld;
#pragma unroll
        for (int j = 0; j < 8; j++) {
            float4 qv = *(const float4*)(qp + j * 4);
            *(float4*)&qs[qls * 132 + qld + j * 4] = qv;
        }
        __syncthreads();
        unsigned long long dot2[4][2];
#pragma unroll
        for (int i = 0; i < 4; i++) { dot2[i][0] = 0ULL; dot2[i][1] = 0ULL; }
#pragma unroll 8
        for (int dd = 0; dd < DIi; dd++) {
            float4 kv = *(const float4*)&kst[dd * 68 + ti];
            unsigned long long k01 = pk2(kv.x, kv.y);
            unsigned long long k23 = pk2(kv.z, kv.w);
#pragma unroll
            for (int i = 0; i < 4; i++) {
                float qv = qs[(si + i) * 132 + dd];
                unsigned long long q2 = pk2(qv, qv);
                fma2(dot2[i][0], q2, k01);
                fma2(dot2[i][1], q2, k23);
            }
        }
#pragma unroll
        for (int i = 0; i < 4; i++) {
            float wv = ws[(si + i) * 33 + h];
            float2 d01 = upk2(dot2[i][0]);
            float2 d23 = upk2(dot2[i][1]);
            score[i][0] += fmaxf(d01.x * INV_SQRT_DI, 0.f) * wv;
            score[i][1] += fmaxf(d01.y * INV_SQRT_DI, 0.f) * wv;
            score[i][2] += fmaxf(d23.x * INV_SQRT_DI, 0.f) * wv;
            score[i][3] += fmaxf(d23.y * INV_SQRT_DI, 0.f) * wv;
        }
    }
#pragma unroll
    for (int i = 0; i < 4; i++) {
        int s = s0 + si + i;
#pragma unroll
        for (int j = 0; j < 4; j++) {
            int t = t0 + ti + j;
            if (t <= s) iscore[(size_t)s * SQ + t] = score[i][j];
        }
    }
}

// ---------------- exact top-512: radix select + fully parallel ordered fill ----------------
__device__ __forceinline__ unsigned forder(float f)
{
    unsigned u = __float_as_uint(f);
    return (u & 0x80000000u) ? ~u : (u | 0x80000000u);
}

__global__ __launch_bounds__(256) void topk_kernel(const float* __restrict__ iscore,
                                                   int* __restrict__ tidx, int* __restrict__ tcnt)
{
    int s = blockIdx.x;
    int n = s + 1;
    int tid = threadIdx.x;
    const float* row = iscore + (size_t)s * SQ;
    int* out = tidx + (size_t)s * TOPK;
    if (n <= TOPK) {
        for (int t = tid; t < n; t += 256) out[t] = t;
        if (tid == 0) tcnt[s] = n;
        return;
    }
    __shared__ int hist[256];
    __shared__ unsigned s_pref;
    __shared__ int s_k;
    __shared__ int sc[256];
    if (tid == 0) { s_pref = 0u; s_k = TOPK; }
    __syncthreads();
    for (int pass = 0; pass < 4; pass++) {
        int sh = 24 - 8 * pass;
        unsigned hmask = (pass == 0) ? 0u : (0xFFFFFFFFu << (sh + 8));
        hist[tid] = 0;
        __syncthreads();
        unsigned pref = s_pref;
        for (int t = tid; t < n; t += 256) {
            unsigned u = forder(row[t]);
            if ((u & hmask) == pref) atomicAdd(&hist[(u >> sh) & 255u], 1);
        }
        __syncthreads();
        if (tid == 0) {
            int k = s_k, c = 0, j = 255;
            for (; j >= 0; j--) {
                if (c + hist[j] >= k) break;
                c += hist[j];
            }
            s_k = k - c;
            s_pref = s_pref | ((unsigned)j << sh);
        }
        __syncthreads();
    }
    unsigned uthr = s_pref;
    int kneed = s_k;
    int chunk = (n + 255) / 256;
    int beg = tid * chunk;
    int end = beg + chunk; if (end > n) end = n;
    int cntg = 0, cnte = 0;
    for (int t = beg; t < end; t++) {
        unsigned u = forder(row[t]);
        if (u > uthr) cntg++;
        else if (u == uthr) cnte++;
    }
    sc[tid] = cntg;
    __syncthreads();
    for (int o = 1; o < 256; o <<= 1) {
        int v = (tid >= o) ? sc[tid - o] : 0;
        __syncthreads();
        sc[tid] += v;
        __syncthreads();
    }
    int offg = sc[tid] - cntg;
    int totalg = sc[255];
    __syncthreads();
    sc[tid] = cnte;
    __syncthreads();
    for (int o = 1; o < 256; o <<= 1) {
        int v = (tid >= o) ? sc[tid - o] : 0;
        __syncthreads();
        sc[tid] += v;
        __syncthreads();
    }
    int offe = sc[tid] - cnte;
    for (int t = beg; t < end; t++) {
        unsigned u = forder(row[t]);
        if (u > uthr) {
            out[offg++] = t;
        } else if (u == uthr) {
            int rank = offe++;
            if (rank < kneed) out[totalg + rank] = t;  // ties: lowest t first
        }
    }
    if (tid == 0) tcnt[s] = TOPK;
}

// ---------------- sparse attention per (s, h) ----------------
__global__ __launch_bounds__(256) void attn_kernel(
    const float* __restrict__ q, const float* __restrict__ k, const float* __restrict__ v,
    const int* __restrict__ tidx, const int* __restrict__ tcnt, float* __restrict__ out)
{
    int s = blockIdx.x, h = blockIdx.y;
    int tid = threadIdx.x, lane = tid & 31, wp = tid >> 5;
    int n = tcnt[s];
    __shared__ float qs[DQK];
    __shared__ float lg[TOPK];
    __shared__ int   ix[TOPK];
    __shared__ float red[8];
    __shared__ float accs[128];
    if (tid < DQK) qs[tid] = q[(size_t)s * (H * DQK) + h * DQK + tid];
    for (int j = tid; j < n; j += 256) ix[j] = tidx[(size_t)s * TOPK + j];
    __syncthreads();
    for (int j = wp; j < n; j += 8) {
        const float* kp = k + (size_t)ix[j] * (H * DQK) + h * DQK;
        float d = 0.f;
#pragma unroll
        for (int c = 0; c < DQK / 32; c++) d += qs[lane + c * 32] * kp[lane + c * 32];
#pragma unroll
        for (int o = 16; o; o >>= 1) d += __shfl_xor_sync(0xffffffffu, d, o);
        if (lane == 0) lg[j] = d * INV_SQRT_DQK;
    }
    __syncthreads();
    float m = -FLT_MAX;
    for (int j = tid; j < n; j += 256) m = fmaxf(m, lg[j]);
#pragma unroll
    for (int o = 16; o; o >>= 1) m = fmaxf(m, __shfl_xor_sync(0xffffffffu, m, o));
    if (lane == 0) red[wp] = m;
    __syncthreads();
    m = red[0];
#pragma unroll
    for (int i = 1; i < 8; i++) m = fmaxf(m, red[i]);
    __syncthreads();
    float ssum = 0.f;
    for (int j = tid; j < n; j += 256) { float e = __expf(lg[j] - m); lg[j] = e; ssum += e; }
#pragma unroll
    for (int o = 16; o; o >>= 1) ssum += __shfl_xor_sync(0xffffffffu, ssum, o);
    if (lane == 0) red[wp] = ssum;
    __syncthreads();
    float tot = 0.f;
#pragma unroll
    for (int i = 0; i < 8; i++) tot += red[i];
    float inv = 1.f / tot;
    int d = tid & 127, half = tid >> 7;
    float acc = 0.f;
#pragma unroll 4
    for (int j = half; j < n; j += 2)
        acc += lg[j] * v[(size_t)ix[j] * (H * DV) + h * DV + d];
    if (half == 1) accs[d] = acc;
    __syncthreads();
    if (half == 0)
        out[(size_t)s * (H * DV) + h * DV + d] = (acc + accs[d]) * inv;
}

// ---------------- host launcher ----------------
extern "C" void kernel_launch(void* const* d_in, const int* in_sizes, int n_in,
                              void* d_out, int out_size)
{
    const float *hidden, *cosp, *sinp, *wq_a, *q_norm_w, *wq_b, *wkv_a, *kv_norm_w,
                *wkv_b, *wo, *idx_wq_b, *idx_wk, *idx_kn_w, *idx_kn_b, *idx_wproj;
    if (n_in >= 2 && in_sizes[1] == 3145728) {
        hidden    = (const float*)d_in[0];
        wq_a      = (const float*)d_in[1];
        q_norm_w  = (const float*)d_in[2];
        wq_b      = (const float*)d_in[3];
        wkv_a     = (const float*)d_in[4];
        kv_norm_w = (const float*)d_in[5];
        wkv_b     = (const float*)d_in[6];
        wo        = (const float*)d_in[7];
        idx_wq_b  = (const float*)d_in[8];
        idx_wk    = (const float*)d_in[9];
        idx_kn_w  = (const float*)d_in[10];
        idx_kn_b  = (const float*)d_in[11];
        idx_wproj = (const float*)d_in[12];
        cosp      = (const float*)d_in[13];
        sinp      = (const float*)d_in[14];
    } else {
        hidden    = (const float*)d_in[0];
        cosp      = (const float*)d_in[1];
        sinp      = (const float*)d_in[2];
        wq_a      = (const float*)d_in[4];
        q_norm_w  = (const float*)d_in[5];
        wq_b      = (const float*)d_in[6];
        wkv_a     = (const float*)d_in[7];
        kv_norm_w = (const float*)d_in[8];
        wkv_b     = (const float*)d_in[9];
        wo        = (const float*)d_in[10];
        idx_wq_b  = (const float*)d_in[11];
        idx_wk    = (const float*)d_in[12];
        idx_kn_w  = (const float*)d_in[13];
        idx_kn_b  = (const float*)d_in[14];
        idx_wproj = (const float*)d_in[15];
    }

    float *qr, *q, *kvall, *kv, *kpe, *kvp, *k, *v, *qi, *ki, *wtsb, *iscore, *attnb;
    int *tix, *tcn;
    cudaGetSymbolAddress((void**)&qr,    g_qr);
    cudaGetSymbolAddress((void**)&q,     g_q);
    cudaGetSymbolAddress((void**)&kvall, g_kvall);
    cudaGetSymbolAddress((void**)&kv,    g_kv);
    cudaGetSymbolAddress((void**)&kpe,   g_kpe);
    cudaGetSymbolAddress((void**)&kvp,   g_kvp);
    cudaGetSymbolAddress((void**)&k,     g_k);
    cudaGetSymbolAddress((void**)&v,     g_v);
    cudaGetSymbolAddress((void**)&qi,    g_qi);
    cudaGetSymbolAddress((void**)&ki,    g_ki);
    cudaGetSymbolAddress((void**)&wtsb,  g_wts);
    cudaGetSymbolAddress((void**)&iscore,g_iscore);
    cudaGetSymbolAddress((void**)&attnb, g_attn);
    cudaGetSymbolAddress((void**)&tix,   g_tidx);
    cudaGetSymbolAddress((void**)&tcn,   g_tcnt);

    const int ISMEM = (128 * 68 + 64 * 132 + 64 * 33) * 4;   // 77056 B
    cudaFuncSetAttribute(indexer_kernel, cudaFuncAttributeMaxDynamicSharedMemorySize, ISMEM);

    // ---- indexer-critical path (bit-identical to the passing fp32 baseline) ----
    // 1. qr = rmsnorm(hidden @ wq_a.T)   [feeds qi -> iscore -> top-k]
    sgemm_nt<<<dim3(16, 12), 256>>>(hidden, wq_a, qr, SQ, QRr, DM);
    rmsnorm_kernel<<<SQ, 256>>>(qr, q_norm_w, qr, QRr, QRr, QRr, 1e-6f);

    // 5. qi = rope_half(qr @ idx_wq_b.T)
    sgemm_nt<<<dim3(16, 32), 256>>>(qr, idx_wq_b, qi, SQ, HIi * DIi, QRr);
    rope_half_qi_kernel<<<(SQ * HIi * 32 + 255) / 256, 256>>>(qi, cosp, sinp);

    // 6. ki = rope_half(layernorm(hidden @ idx_wk.T))
    gemm_warpdot<<<(SQ * DIi * 32) / 256, 256>>>(hidden, idx_wk, ki, SQ, DIi, DM, 1.f);
    layernorm128_kernel<<<SQ, 128>>>(ki, idx_kn_w, idx_kn_b);
    rope_half_ki_kernel<<<(SQ * 32 + 255) / 256, 256>>>(ki, cosp, sinp);

    // 7. wts = hidden @ idx_wproj.T * HI^-0.5
    gemm_warpdot<<<(SQ * HIi * 32) / 256, 256>>>(hidden, idx_wproj, wtsb, SQ, HIi, DM, INV_SQRT_HI);

    // ---- value path (smooth; bf16x6 tensor cores) ----
    // 2. q = rope(qr @ wq_b.T)
    gemm_bf16x6<<<dim3((H * DQK) / 64, 16), 256>>>(qr, wq_b, q, SQ, H * DQK, QRr);
    rope_inter_q<<<(SQ * H * 32 + 255) / 256, 256>>>(q, cosp, sinp);

    // 3. kv_all = hidden @ wkv_a.T ; kv = rmsnorm ; kpe = rope
    gemm_bf16x6<<<dim3((KRr + DRR) / 64, 16), 256>>>(hidden, wkv_a, kvall, SQ, KRr + DRR, DM);
    rmsnorm_kernel<<<SQ, 256>>>(kvall, kv_norm_w, kv, KRr, KRr + DRR, KRr, 1e-6f);
    rope_inter_kpe<<<(SQ * 32 + 255) / 256, 256>>>(kvall, cosp, sinp, kpe);

    // 4. kvp = kv @ wkv_b.T ; split k/v
    gemm_bf16x6<<<dim3((H * (DN + DV)) / 64, 16), 256>>>(kv, wkv_b, kvp, SQ, H * (DN + DV), KRr);
    pack_k_kernel<<<(SQ * H * DQK + 255) / 256, 256>>>(kvp, kpe, k);
    pack_v_kernel<<<(SQ * H * DV + 255) / 256, 256>>>(kvp, v);

    // 8. indexer scores (causal)
    indexer_kernel<<<dim3(32, 32), 256, ISMEM>>>(qi, ki, wtsb, iscore);

    // 9. exact top-512 per row
    topk_kernel<<<SQ, 256>>>(iscore, tix, tcn);

    // 10. sparse attention
    attn_kernel<<<dim3(SQ, H), 256>>>(q, k, v, tix, tcn, attnb);

    // 11. output projection
    gemm_bf16x6<<<dim3(DM / 64, 16), 256>>>(attnb, wo, (float*)d_out, SQ, DM, DM);
}